// round 1
// baseline (speedup 1.0000x reference)
#include <cuda_runtime.h>
#include <cstddef>

#define NPIX 2304          // 48*48
#define HPW  48
#define BSZ  4
#define CDIM 256
#define NH   8
#define HD   32
#define ATT_SCALE 0.17677669529663687f   // 32^-0.5

// ---------------- scratch (module-load allocated, legal) ----------------
__device__ float g_qk[(size_t)BSZ * 512 * NPIX];   // [B,512,N]  (q: h*64..h*64+31, k: +32)
__device__ float g_v4[(size_t)BSZ * CDIM * NPIX];  // [B,256,N]
__device__ float g_pe[(size_t)BSZ * CDIM * NPIX];
__device__ float g_o [(size_t)BSZ * CDIM * NPIX];

// ---------------- 1x1 conv as GEMM: Y[b,o,n] = bias[o] + sum_c W[o,c]*(A+A2)[b,c,n]
// grid: (NPIX/64, O/64, B), block 256 (16x16), 4x4 microtile per thread
__global__ __launch_bounds__(256) void conv1x1_kernel(
    const float* __restrict__ A, const float* __restrict__ A2,
    const float* __restrict__ W, const float* __restrict__ bias,
    float* __restrict__ Y, int O)
{
    __shared__ float w_s[32][65];   // [cc][oo], pad 65 to kill write conflicts
    __shared__ float a_s[32][64];   // [cc][nn]

    const int b  = blockIdx.z;
    const int o0 = blockIdx.y * 64;
    const int n0 = blockIdx.x * 64;
    const int t  = threadIdx.x;
    const int tx = t & 15;          // n direction
    const int ty = t >> 4;          // o direction

    const float* Ab  = A  + (size_t)b * CDIM * NPIX;
    const float* A2b = A2 ? A2 + (size_t)b * CDIM * NPIX : nullptr;

    float acc[4][4];
    #pragma unroll
    for (int i = 0; i < 4; i++)
        #pragma unroll
        for (int j = 0; j < 4; j++) acc[i][j] = 0.f;

    for (int c0 = 0; c0 < CDIM; c0 += 32) {
        __syncthreads();
        #pragma unroll
        for (int r = 0; r < 8; r++) {
            int e = t + r * 256;
            // W tile: 32c x 64o
            {
                int oo = e >> 5, cc = e & 31;
                w_s[cc][oo] = W[(size_t)(o0 + oo) * CDIM + c0 + cc];
            }
            // A tile: 32c x 64n
            {
                int cc = e >> 6, nn = e & 63;
                float v = Ab[(size_t)(c0 + cc) * NPIX + n0 + nn];
                if (A2b) v += A2b[(size_t)(c0 + cc) * NPIX + n0 + nn];
                a_s[cc][nn] = v;
            }
        }
        __syncthreads();

        #pragma unroll
        for (int k = 0; k < 32; k++) {
            float wv[4], av[4];
            #pragma unroll
            for (int i = 0; i < 4; i++) wv[i] = w_s[k][ty + 16 * i];
            #pragma unroll
            for (int j = 0; j < 4; j++) av[j] = a_s[k][tx + 16 * j];
            #pragma unroll
            for (int i = 0; i < 4; i++)
                #pragma unroll
                for (int j = 0; j < 4; j++) acc[i][j] += wv[i] * av[j];
        }
    }

    #pragma unroll
    for (int i = 0; i < 4; i++) {
        int o = o0 + ty + 16 * i;
        float bo = bias[o];
        #pragma unroll
        for (int j = 0; j < 4; j++) {
            int n = n0 + tx + 16 * j;
            Y[((size_t)b * O + o) * NPIX + n] = acc[i][j] + bo;
        }
    }
}

// ---------------- depthwise 3x3, SAME padding; grid = B*C blocks, 256 thr
__global__ __launch_bounds__(256) void dwconv_kernel(
    const float* __restrict__ v4, const float* __restrict__ w_pe,
    const float* __restrict__ b_pe, float* __restrict__ pe)
{
    __shared__ float plane[NPIX];
    const int bc = blockIdx.x;
    const int c  = bc & (CDIM - 1);
    const int t  = threadIdx.x;

    const float* src = v4 + (size_t)bc * NPIX;
    #pragma unroll
    for (int r = 0; r < 9; r++) plane[t + r * 256] = src[t + r * 256];

    float w[9];
    #pragma unroll
    for (int k = 0; k < 9; k++) w[k] = w_pe[c * 9 + k];
    const float bias = b_pe[c];
    __syncthreads();

    float* dst = pe + (size_t)bc * NPIX;
    #pragma unroll
    for (int r = 0; r < 9; r++) {
        int idx = t + r * 256;
        int y = idx / HPW, x = idx - y * HPW;
        float s = bias;
        #pragma unroll
        for (int dy = 0; dy < 3; dy++) {
            int yy = y + dy - 1;
            if (yy < 0 || yy >= HPW) continue;
            #pragma unroll
            for (int dx = 0; dx < 3; dx++) {
                int xx = x + dx - 1;
                if (xx < 0 || xx >= HPW) continue;
                s += plane[yy * HPW + xx] * w[dy * 3 + dx];
            }
        }
        dst[idx] = s;
    }
}

// ---------------- flash attention: 1 query/thread, online softmax
// grid (N/256, B*NH), block 256. K/V tiles of 64 j's staged in smem.
__global__ __launch_bounds__(256) void attn_kernel(
    const float* __restrict__ qk, const float* __restrict__ v4,
    float* __restrict__ o)
{
    __shared__ __align__(16) float k_s[64][36];  // 36 floats/row: 16B-aligned rows, good banks
    __shared__ __align__(16) float v_s[64][36];

    const int bh = blockIdx.y;
    const int b = bh >> 3, h = bh & 7;
    const int t = threadIdx.x;
    const int i = blockIdx.x * 256 + t;

    const float* qb = qk + ((size_t)b * 512 + h * 64) * NPIX;
    const float* kb = qb + (size_t)32 * NPIX;
    const float* vb = v4 + ((size_t)b * CDIM + h * HD) * NPIX;

    float q[32];
    #pragma unroll
    for (int d = 0; d < 32; d++) q[d] = qb[(size_t)d * NPIX + i] * ATT_SCALE;

    float m = -1e30f, l = 0.f;
    float acc[32];
    #pragma unroll
    for (int d = 0; d < 32; d++) acc[d] = 0.f;

    for (int j0 = 0; j0 < NPIX; j0 += 64) {
        __syncthreads();
        #pragma unroll
        for (int r = 0; r < 8; r++) {
            int e = t + r * 256;
            int d = e >> 6, jj = e & 63;        // coalesced in jj
            k_s[jj][d] = kb[(size_t)d * NPIX + j0 + jj];
            v_s[jj][d] = vb[(size_t)d * NPIX + j0 + jj];
        }
        __syncthreads();

        for (int jj = 0; jj < 64; jj++) {
            const float4* kr = (const float4*)&k_s[jj][0];
            float s = 0.f;
            #pragma unroll
            for (int dq = 0; dq < 8; dq++) {
                float4 kv = kr[dq];              // broadcast across warp
                s += q[4*dq+0] * kv.x + q[4*dq+1] * kv.y
                   + q[4*dq+2] * kv.z + q[4*dq+3] * kv.w;
            }
            float mn = fmaxf(m, s);
            if (mn > m) {                        // rare (~log N times)
                float cor = __expf(m - mn);
                l *= cor;
                #pragma unroll
                for (int d = 0; d < 32; d++) acc[d] *= cor;
                m = mn;
            }
            float p = __expf(s - m);
            l += p;
            const float4* vr = (const float4*)&v_s[jj][0];
            #pragma unroll
            for (int dq = 0; dq < 8; dq++) {
                float4 vv = vr[dq];
                acc[4*dq+0] += p * vv.x;
                acc[4*dq+1] += p * vv.y;
                acc[4*dq+2] += p * vv.z;
                acc[4*dq+3] += p * vv.w;
            }
        }
    }

    const float inv = 1.f / l;
    float* ob = o + ((size_t)b * CDIM + h * HD) * NPIX + i;
    #pragma unroll
    for (int d = 0; d < 32; d++) ob[(size_t)d * NPIX] = acc[d] * inv;
}

// ---------------- launch ----------------
extern "C" void kernel_launch(void* const* d_in, const int* in_sizes, int n_in,
                              void* d_out, int out_size)
{
    const float* x      = (const float*)d_in[0];
    const float* w_qk   = (const float*)d_in[1];
    const float* b_qk   = (const float*)d_in[2];
    const float* w_v    = (const float*)d_in[3];
    const float* b_v    = (const float*)d_in[4];
    const float* w_pe   = (const float*)d_in[5];
    const float* b_pe   = (const float*)d_in[6];
    const float* w_proj = (const float*)d_in[7];
    const float* b_proj = (const float*)d_in[8];
    float* out = (float*)d_out;

    float *qkp, *v4p, *pep, *op;
    cudaGetSymbolAddress((void**)&qkp, g_qk);
    cudaGetSymbolAddress((void**)&v4p, g_v4);
    cudaGetSymbolAddress((void**)&pep, g_pe);
    cudaGetSymbolAddress((void**)&op,  g_o);

    dim3 blk(256);
    // qk = conv1x1(x, w_qk)      -> [B,512,N]
    conv1x1_kernel<<<dim3(NPIX/64, 512/64, BSZ), blk>>>(x, nullptr, w_qk, b_qk, qkp, 512);
    // v4 = conv1x1(x, w_v)       -> [B,256,N]
    conv1x1_kernel<<<dim3(NPIX/64, CDIM/64, BSZ), blk>>>(x, nullptr, w_v, b_v, v4p, CDIM);
    // pe = dwconv3x3(v4)
    dwconv_kernel<<<BSZ * CDIM, blk>>>(v4p, w_pe, b_pe, pep);
    // o  = attention(q,k,v)
    attn_kernel<<<dim3(NPIX/256, BSZ * NH), blk>>>(qkp, v4p, op);
    // out = conv1x1(o + pe, w_proj)
    conv1x1_kernel<<<dim3(NPIX/64, CDIM/64, BSZ), blk>>>(op, pep, w_proj, b_proj, out, CDIM);
}